// round 11
// baseline (speedup 1.0000x reference)
#include <cuda_runtime.h>
#include <cuda_fp16.h>
#include <cstdint>

#define MARGIN 0.3f
#define DIM  128
#define TILE 128
#define MAXN 4096
#define MAXT (MAXN / TILE)
#define MAXPAIR (MAXT * (MAXT + 1) / 2)
#define CT   16384                 // image chunk tile: 128 rows x 64 fp16 cols (SW128)

// ---- dynamic smem layout (bytes) ----
#define SM_CBI   0                 // 128 f
#define SM_N1BI  512
#define SM_N2BI  1024
#define SM_CBJH  1536              // 64 f
#define SM_N1BJH 1792
#define SM_N2BJH 2048
#define SM_RMI   2304              // 128 u
#define SM_RMJH  2816              // 64 u
#define SM_SSUM  3072              // 8 f
#define SM_OPS   4096              // 96KB operand region, 1024-aligned
#define SMEM_TOTAL (SM_OPS + 96 * 1024)

// phase1 (all prefetched): A hi full-K [0,32K) (c0,c1); B regions 16K each (c0@+0, c1@+8K)
#define P1_AH  0
#define P1_B1H (32 * 1024)
#define P1_B1L (48 * 1024)
#define P1_B2H (64 * 1024)
#define P1_B2L (80 * 1024)
// phase2 double buffer (reuses [0,80K) after phase1 reads done): A2H 8K, B2H 16K, B2L 16K
#define P2_BUF(c) ((c) * 40 * 1024)
#define P2_A2H 0
#define P2_B2H (8 * 1024)
#define P2_B2L (24 * 1024)

__device__ float g_n1[MAXN], g_n2[MAXN], g_C[MAXN];
__device__ unsigned int g_rowmax[MAXN];      // zero at load; finalizer re-zeros
__device__ float g_partial[2 * MAXPAIR];
__device__ unsigned int g_work;              // work ticket; finalizer re-zeros
__device__ unsigned int g_done;              // CTA done counter; finalizer re-zeros

// pre-swizzled fp16 hi/lo images: [tile][chunk][16KB]
__device__ __align__(16) unsigned char g_img_p1h[MAXT * 2 * CT];
__device__ __align__(16) unsigned char g_img_p1l[MAXT * 2 * CT];
__device__ __align__(16) unsigned char g_img_p2h[MAXT * 2 * CT];
__device__ __align__(16) unsigned char g_img_p2l[MAXT * 2 * CT];

__device__ __forceinline__ uint32_t smem_u32(const void* p) {
    uint32_t a;
    asm("{ .reg .u64 t; cvta.to.shared.u64 t, %1; cvt.u32.u64 %0, t; }" : "=r"(a) : "l"(p));
    return a;
}
__device__ __forceinline__ int swz(int row, int kc) {
    int b = row * 128 + kc * 2;
    return b ^ ((b >> 3) & 0x70);
}
__device__ __forceinline__ uint32_t taddrA(uint32_t base0, int row, int kcol) {
    return base0 + ((kcol >> 6) << 14) + swz(row, kcol & 63);
}
__device__ __forceinline__ void ldsm4(uint32_t addr, uint32_t r[4]) {
    asm volatile("ldmatrix.sync.aligned.m8n8.x4.shared.b16 {%0,%1,%2,%3}, [%4];"
                 : "=r"(r[0]), "=r"(r[1]), "=r"(r[2]), "=r"(r[3]) : "r"(addr));
}
__device__ __forceinline__ void cp16(uint32_t saddr, const void* g) {
    asm volatile("cp.async.cg.shared.global [%0], [%1], 16;" :: "r"(saddr), "l"(g));
}
#define CP_COMMIT() asm volatile("cp.async.commit_group;" ::: "memory")
#define CP_WAIT0()  asm volatile("cp.async.wait_group 0;" ::: "memory")
#define CP_WAIT1()  asm volatile("cp.async.wait_group 1;" ::: "memory")

#define MMA(d, a, b)                                                               \
    asm volatile("mma.sync.aligned.m16n8k16.row.col.f32.f16.f16.f32 "              \
                 "{%0,%1,%2,%3},{%4,%5,%6,%7},{%8,%9},{%0,%1,%2,%3};"              \
                 : "+f"((d)[0]), "+f"((d)[1]), "+f"((d)[2]), "+f"((d)[3])          \
                 : "r"((a)[0]), "r"((a)[1]), "r"((a)[2]), "r"((a)[3]),             \
                   "r"((b)[0]), "r"((b)[1]))

union HU { __half2 h; uint32_t u; };

__device__ __forceinline__ void cpa(uint32_t sdst, const unsigned char* gsrc, int bytes, int tid) {
    for (int t = tid * 16; t < bytes; t += 4096) cp16(sdst + t, gsrc + t);
}

__device__ __forceinline__ void decode(int w, int nt, int& bi, int& bj, int& h) {
    int pairid = w >> 1;
    h = w & 1;
    bi = 0;
    int rem = pairid;
    while (rem >= nt - bi) { rem -= (nt - bi); bi++; }
    bj = bi + rem;
}

// full phase1 prologue: g0 = A c0+c1 + all B c0 (64K); g1 = all B c1 (32K)
__device__ __forceinline__ void load_item(uint32_t OPS, int bi, int bj, int h, int tid) {
    size_t b0 = (size_t)(bj * 2 + 0) * CT + h * 8192;
    size_t b1 = (size_t)(bj * 2 + 1) * CT + h * 8192;
    cpa(OPS + P1_AH, g_img_p1h + (size_t)(bi * 2) * CT, 2 * CT, tid);
    cpa(OPS + P1_B1H, g_img_p1h + b0, 8192, tid);
    cpa(OPS + P1_B1L, g_img_p1l + b0, 8192, tid);
    cpa(OPS + P1_B2H, g_img_p2h + b0, 8192, tid);
    cpa(OPS + P1_B2L, g_img_p2l + b0, 8192, tid);
    CP_COMMIT();                                                   // g0
    cpa(OPS + P1_B1H + 8192, g_img_p1h + b1, 8192, tid);
    cpa(OPS + P1_B1L + 8192, g_img_p1l + b1, 8192, tid);
    cpa(OPS + P1_B2H + 8192, g_img_p2h + b1, 8192, tid);
    cpa(OPS + P1_B2L + 8192, g_img_p2l + b1, 8192, tid);
    CP_COMMIT();                                                   // g1
}

// fused 4 ksteps: one A-frag load feeds both grams (B1->acc1, B2->acc2)
__device__ __forceinline__ void fused4(
    uint32_t AH, uint32_t B1H, uint32_t B1L, uint32_t B2H, uint32_t B2L,
    int kAbase, int arow, int akoff, int brow, int bkoff,
    float (&acc1)[2][4][4], float (&acc2)[2][4][4])
{
#pragma unroll
    for (int ks = 0; ks < 4; ks++) {
        const int kA = kAbase + ks * 16;
        const int kB = ks * 16;
        uint32_t ah[2][4];
#pragma unroll
        for (int mf = 0; mf < 2; mf++)
            ldsm4(taddrA(AH, arow + mf * 16, kA + akoff), ah[mf]);
        {
            uint32_t bh[4][2], bl[4][2];
#pragma unroll
            for (int np = 0; np < 2; np++) {
                uint32_t t4[4];
                ldsm4(B1H + swz(brow + np * 16, kB + bkoff), t4);
                bh[2*np][0]=t4[0]; bh[2*np][1]=t4[1]; bh[2*np+1][0]=t4[2]; bh[2*np+1][1]=t4[3];
                ldsm4(B1L + swz(brow + np * 16, kB + bkoff), t4);
                bl[2*np][0]=t4[0]; bl[2*np][1]=t4[1]; bl[2*np+1][0]=t4[2]; bl[2*np+1][1]=t4[3];
            }
#pragma unroll
            for (int mf = 0; mf < 2; mf++)
#pragma unroll
                for (int nf = 0; nf < 4; nf++) {
                    MMA(acc1[mf][nf], ah[mf], bh[nf]);
                    MMA(acc1[mf][nf], ah[mf], bl[nf]);
                }
        }
        {
            uint32_t bh[4][2], bl[4][2];
#pragma unroll
            for (int np = 0; np < 2; np++) {
                uint32_t t4[4];
                ldsm4(B2H + swz(brow + np * 16, kB + bkoff), t4);
                bh[2*np][0]=t4[0]; bh[2*np][1]=t4[1]; bh[2*np+1][0]=t4[2]; bh[2*np+1][1]=t4[3];
                ldsm4(B2L + swz(brow + np * 16, kB + bkoff), t4);
                bl[2*np][0]=t4[0]; bl[2*np][1]=t4[1]; bl[2*np+1][0]=t4[2]; bl[2*np+1][1]=t4[3];
            }
#pragma unroll
            for (int mf = 0; mf < 2; mf++)
#pragma unroll
                for (int nf = 0; nf < 4; nf++) {
                    MMA(acc2[mf][nf], ah[mf], bh[nf]);
                    MMA(acc2[mf][nf], ah[mf], bl[nf]);
                }
        }
    }
}

// single-gram 4 ksteps (phase2)
__device__ __forceinline__ void group4(
    uint32_t AH, uint32_t BH, uint32_t BL, int kAbase,
    int arow, int akoff, int brow, int bkoff, float (&acc)[2][4][4])
{
#pragma unroll
    for (int ks = 0; ks < 4; ks++) {
        const int kA = kAbase + ks * 16;
        const int kB = ks * 16;
        uint32_t ah[2][4];
#pragma unroll
        for (int mf = 0; mf < 2; mf++)
            ldsm4(taddrA(AH, arow + mf * 16, kA + akoff), ah[mf]);
        uint32_t bh[4][2], bl[4][2];
#pragma unroll
        for (int np = 0; np < 2; np++) {
            uint32_t t4[4];
            ldsm4(BH + swz(brow + np * 16, kB + bkoff), t4);
            bh[2*np][0]=t4[0]; bh[2*np][1]=t4[1]; bh[2*np+1][0]=t4[2]; bh[2*np+1][1]=t4[3];
            ldsm4(BL + swz(brow + np * 16, kB + bkoff), t4);
            bl[2*np][0]=t4[0]; bl[2*np][1]=t4[1]; bl[2*np+1][0]=t4[2]; bl[2*np+1][1]=t4[3];
        }
#pragma unroll
        for (int mf = 0; mf < 2; mf++)
#pragma unroll
            for (int nf = 0; nf < 4; nf++) {
                MMA(acc[mf][nf], ah[mf], bh[nf]);
                MMA(acc[mf][nf], ah[mf], bl[nf]);
            }
    }
}

__device__ __forceinline__ void epi_normal(
    float (&acc)[2][4][4], const float* Crow, const float* ncol,
    int wm, int wn, int qr, int qc, int l, bool dz, int rbase, int cbase,
    unsigned int* srm, float& sum)
{
    float Cr[2][2], nc[4][2];
#pragma unroll
    for (int mf = 0; mf < 2; mf++) {
        int r0 = wm * 32 + mf * 16 + qr;
        Cr[mf][0] = Crow[r0]; Cr[mf][1] = Crow[r0 + 8];
    }
#pragma unroll
    for (int nf = 0; nf < 4; nf++) {
        int c0 = wn * 32 + nf * 8 + qc;
        nc[nf][0] = ncol[c0]; nc[nf][1] = ncol[c0 + 1];
    }
    float rmax[2][2] = {{0.f, 0.f}, {0.f, 0.f}};
#pragma unroll
    for (int mf = 0; mf < 2; mf++)
#pragma unroll
        for (int nf = 0; nf < 4; nf++)
#pragma unroll
            for (int e = 0; e < 4; e++) {
                int rr = e >> 1, cc = e & 1;
                float v = fmaxf(Cr[mf][rr] - nc[nf][cc] + 2.f * acc[mf][nf][e], 0.f);
                if (dz) {
                    int rl = rbase + wm * 32 + mf * 16 + qr + rr * 8;
                    int cl = cbase + wn * 32 + nf * 8 + qc + cc;
                    if (rl == cl) v = 0.f;
                }
                sum += v;
                rmax[mf][rr] = fmaxf(rmax[mf][rr], v);
            }
#pragma unroll
    for (int m = 1; m <= 2; m <<= 1)
#pragma unroll
        for (int mf = 0; mf < 2; mf++) {
            rmax[mf][0] = fmaxf(rmax[mf][0], __shfl_xor_sync(0xffffffffu, rmax[mf][0], m));
            rmax[mf][1] = fmaxf(rmax[mf][1], __shfl_xor_sync(0xffffffffu, rmax[mf][1], m));
        }
    if ((l & 3) == 0) {
#pragma unroll
        for (int mf = 0; mf < 2; mf++) {
            atomicMax(&srm[wm * 32 + mf * 16 + qr],     __float_as_uint(rmax[mf][0]));
            atomicMax(&srm[wm * 32 + mf * 16 + qr + 8], __float_as_uint(rmax[mf][1]));
        }
    }
}

__device__ __forceinline__ void epi_trans(
    float (&acc)[2][4][4], const float* Ccol, const float* nrow,
    int wm, int wn, int qr, int qc, int l,
    unsigned int* srm, float& sum)
{
    float Ct[4][2], nr[2][2];
#pragma unroll
    for (int nf = 0; nf < 4; nf++) {
        int c0 = wn * 32 + nf * 8 + qc;
        Ct[nf][0] = Ccol[c0]; Ct[nf][1] = Ccol[c0 + 1];
    }
#pragma unroll
    for (int mf = 0; mf < 2; mf++) {
        int r0 = wm * 32 + mf * 16 + qr;
        nr[mf][0] = nrow[r0]; nr[mf][1] = nrow[r0 + 8];
    }
    float cmax[4][2] = {{0.f,0.f},{0.f,0.f},{0.f,0.f},{0.f,0.f}};
#pragma unroll
    for (int mf = 0; mf < 2; mf++)
#pragma unroll
        for (int nf = 0; nf < 4; nf++)
#pragma unroll
            for (int e = 0; e < 4; e++) {
                int rr = e >> 1, cc = e & 1;
                float v = fmaxf(Ct[nf][cc] - nr[mf][rr] + 2.f * acc[mf][nf][e], 0.f);
                sum += v;
                cmax[nf][cc] = fmaxf(cmax[nf][cc], v);
            }
#pragma unroll
    for (int m = 4; m <= 16; m <<= 1)
#pragma unroll
        for (int nf = 0; nf < 4; nf++) {
            cmax[nf][0] = fmaxf(cmax[nf][0], __shfl_xor_sync(0xffffffffu, cmax[nf][0], m));
            cmax[nf][1] = fmaxf(cmax[nf][1], __shfl_xor_sync(0xffffffffu, cmax[nf][1], m));
        }
    if (l < 4) {
#pragma unroll
        for (int nf = 0; nf < 4; nf++) {
            int c0 = wn * 32 + nf * 8 + qc;
            atomicMax(&srm[c0],     __float_as_uint(cmax[nf][0]));
            atomicMax(&srm[c0 + 1], __float_as_uint(cmax[nf][1]));
        }
    }
}

// ---- prep: norms/C + pre-swizzled fp16 hi/lo images ----
__global__ void __launch_bounds__(256)
prep_kernel(const float* __restrict__ p1, const float* __restrict__ p2, int n) {
    int row = blockIdx.x * 8 + (threadIdx.x >> 5);
    int lane = threadIdx.x & 31;
    if (row >= n) return;
    float4 a = ((const float4*)(p1 + (size_t)row * DIM))[lane];
    float4 b = ((const float4*)(p2 + (size_t)row * DIM))[lane];

    float n1 = a.x*a.x + a.y*a.y + a.z*a.z + a.w*a.w;
    float n2 = b.x*b.x + b.y*b.y + b.z*b.z + b.w*b.w;
    float dx = a.x-b.x, dy = a.y-b.y, dz = a.z-b.z, dw = a.w-b.w;
    float dap = dx*dx + dy*dy + dz*dz + dw*dw;
#pragma unroll
    for (int m = 16; m; m >>= 1) {
        n1 += __shfl_xor_sync(0xffffffffu, n1, m);
        n2 += __shfl_xor_sync(0xffffffffu, n2, m);
        dap += __shfl_xor_sync(0xffffffffu, dap, m);
    }
    if (lane == 0) {
        g_n1[row] = n1; g_n2[row] = n2; g_C[row] = dap - n1 + MARGIN;
    }

    int tile = row >> 7, lr = row & 127;
    int c4 = lane * 4, chunk = c4 >> 6, lc = c4 & 63;
    size_t off = (size_t)(tile * 2 + chunk) * CT + swz(lr, lc);

    HU h0, h1, l0, l1;
    h0.h = __floats2half2_rn(a.x, a.y);
    h1.h = __floats2half2_rn(a.z, a.w);
    l0.h = __floats2half2_rn(a.x - __low2float(h0.h), a.y - __high2float(h0.h));
    l1.h = __floats2half2_rn(a.z - __low2float(h1.h), a.w - __high2float(h1.h));
    *(uint2*)(g_img_p1h + off) = make_uint2(h0.u, h1.u);
    *(uint2*)(g_img_p1l + off) = make_uint2(l0.u, l1.u);

    h0.h = __floats2half2_rn(b.x, b.y);
    h1.h = __floats2half2_rn(b.z, b.w);
    l0.h = __floats2half2_rn(b.x - __low2float(h0.h), b.y - __high2float(h0.h));
    l1.h = __floats2half2_rn(b.z - __low2float(h1.h), b.w - __high2float(h1.h));
    *(uint2*)(g_img_p2h + off) = make_uint2(h0.u, h1.u);
    *(uint2*)(g_img_p2l + off) = make_uint2(l0.u, l1.u);
}

// ---- main: persistent CTAs, fully-prefetched phase1, fused A-sharing ----
__global__ void __launch_bounds__(256, 2)
triplet_persist_kernel(float* __restrict__ out, int n, int nt, int nwork) {
    extern __shared__ char smem[];
    const uint32_t sbase = smem_u32(smem);
    const int tid = threadIdx.x;
    const int wid = tid >> 5;
    const int l   = tid & 31;

    float* sCbi   = (float*)(smem + SM_CBI);
    float* sn1bi  = (float*)(smem + SM_N1BI);
    float* sn2bi  = (float*)(smem + SM_N2BI);
    float* sCbjH  = (float*)(smem + SM_CBJH);
    float* sn1bjH = (float*)(smem + SM_N1BJH);
    float* sn2bjH = (float*)(smem + SM_N2BJH);
    unsigned int* srm_bi  = (unsigned int*)(smem + SM_RMI);
    unsigned int* srm_bjH = (unsigned int*)(smem + SM_RMJH);
    float* ssum = (float*)(smem + SM_SSUM);
    const uint32_t OPS = sbase + SM_OPS;

    __shared__ int s_w;

    const int wm = wid & 3;
    const int wn = wid >> 2;
    const int qr = l >> 2;
    const int qc = (l & 3) * 2;
    const int arow = wm * 32 + (l & 7) + ((l >> 3) & 1) * 8;
    const int akoff = (l >> 4) * 8;
    const int brow = wn * 32 + (l & 7) + ((l >> 4) << 3);
    const int bkoff = ((l >> 3) & 1) * 8;
    const int wm2 = wid & 1;
    const int wn2 = wid >> 1;
    const int arow2 = wm2 * 32 + (l & 7) + ((l >> 3) & 1) * 8;
    const int brow2 = wn2 * 32 + (l & 7) + ((l >> 4) << 3);

    if (tid == 0) s_w = (int)atomicAdd(&g_work, 1u);
    __syncthreads();
    int w = s_w;
    if (w < nwork) {
        int bi, bj, h; decode(w, nt, bi, bj, h);
        load_item(OPS, bi, bj, h, tid);                 // g0, g1 outstanding
    }

    while (w < nwork) {
        int bi, bj, h; decode(w, nt, bi, bj, h);
        const bool diag = (bi == bj);

        __syncthreads();
        if (tid < 128) {
            srm_bi[tid] = 0u;
            sCbi[tid]  = g_C[bi * TILE + tid];
            sn1bi[tid] = g_n1[bi * TILE + tid];
            sn2bi[tid] = g_n2[bi * TILE + tid];
        } else if (tid < 192) {
            int t = tid - 128;
            srm_bjH[t] = 0u;
            sCbjH[t]  = g_C[bj * TILE + h * 64 + t];
            sn1bjH[t] = g_n1[bj * TILE + h * 64 + t];
            sn2bjH[t] = g_n2[bj * TILE + h * 64 + t];
        } else if (tid == 255) {
            s_w = (int)atomicAdd(&g_work, 1u);          // ticket for NEXT item
        }

        float sum = 0.f;
        float acc1[2][4][4], acc2[2][4][4];
#pragma unroll
        for (int mf = 0; mf < 2; mf++)
#pragma unroll
            for (int nf = 0; nf < 4; nf++)
#pragma unroll
                for (int e = 0; e < 4; e++) { acc1[mf][nf][e] = 0.f; acc2[mf][nf][e] = 0.f; }

        CP_WAIT1();             // g0 (A + B c0) ready
        __syncthreads();        // publishes s_w too
        const int wn_next = s_w;

        // ---- phase1: fused, zero mid-phase reloads ----
        fused4(OPS + P1_AH, OPS + P1_B1H, OPS + P1_B1L, OPS + P1_B2H, OPS + P1_B2L,
               0, arow, akoff, brow, bkoff, acc1, acc2);
        CP_WAIT0();             // g1 (B c1) ready
        __syncthreads();
        fused4(OPS + P1_AH, OPS + P1_B1H + 8192, OPS + P1_B1L + 8192,
               OPS + P1_B2H + 8192, OPS + P1_B2L + 8192,
               64, arow, akoff, brow, bkoff, acc1, acc2);
        __syncthreads();        // all phase1 operand reads done

        if (diag) {
            if (wn_next < nwork) {
                int nbi, nbj, nh; decode(wn_next, nt, nbi, nbj, nh);
                load_item(OPS, nbi, nbj, nh, tid);
            }
            epi_normal(acc1, sCbi, sn1bjH, wm, wn, qr, qc, l, true,
                       bi * TILE, bj * TILE + h * 64, srm_bi, sum);
            epi_normal(acc2, sCbi, sn2bjH, wm, wn, qr, qc, l, true,
                       bi * TILE, bj * TILE + h * 64, srm_bi, sum);
        } else {
            const size_t hoff0 = (size_t)(bj * 2 + 0) * CT + h * 8192;
            const size_t hoff1 = (size_t)(bj * 2 + 1) * CT + h * 8192;
            cpa(OPS + P2_BUF(0) + P2_A2H, g_img_p1h + hoff0, 8192, tid);
            cpa(OPS + P2_BUF(0) + P2_B2H, g_img_p2h + (size_t)(bi * 2 + 0) * CT, CT, tid);
            cpa(OPS + P2_BUF(0) + P2_B2L, g_img_p2l + (size_t)(bi * 2 + 0) * CT, CT, tid);
            CP_COMMIT();

            epi_normal(acc1, sCbi, sn1bjH, wm, wn, qr, qc, l, false,
                       bi * TILE, bj * TILE + h * 64, srm_bi, sum);
            epi_trans(acc1, sCbjH, sn1bi, wm, wn, qr, qc, l, srm_bjH, sum);
            epi_normal(acc2, sCbi, sn2bjH, wm, wn, qr, qc, l, false,
                       bi * TILE, bj * TILE + h * 64, srm_bi, sum);

            float accb[2][4][4];
#pragma unroll
            for (int mf = 0; mf < 2; mf++)
#pragma unroll
                for (int nf = 0; nf < 4; nf++)
#pragma unroll
                    for (int e = 0; e < 4; e++) accb[mf][nf][e] = 0.f;

            CP_WAIT0();
            __syncthreads();
            cpa(OPS + P2_BUF(1) + P2_A2H, g_img_p1h + hoff1, 8192, tid);
            cpa(OPS + P2_BUF(1) + P2_B2H, g_img_p2h + (size_t)(bi * 2 + 1) * CT, CT, tid);
            cpa(OPS + P2_BUF(1) + P2_B2L, g_img_p2l + (size_t)(bi * 2 + 1) * CT, CT, tid);
            CP_COMMIT();

            group4(OPS + P2_BUF(0) + P2_A2H, OPS + P2_BUF(0) + P2_B2H,
                   OPS + P2_BUF(0) + P2_B2L, 0, arow2, akoff, brow2, bkoff, accb);
            CP_WAIT0();
            __syncthreads();
            group4(OPS + P2_BUF(1) + P2_A2H, OPS + P2_BUF(1) + P2_B2H,
                   OPS + P2_BUF(1) + P2_B2L, 0, arow2, akoff, brow2, bkoff, accb);
            __syncthreads();    // all phase2 operand reads done

            if (wn_next < nwork) {
                int nbi, nbj, nh; decode(wn_next, nt, nbi, nbj, nh);
                load_item(OPS, nbi, nbj, nh, tid);
            }
            epi_normal(accb, sCbjH, sn2bi, wm2, wn2, qr, qc, l, false, 0, 0, srm_bjH, sum);
        }

        // ---- publish this item ----
#pragma unroll
        for (int m = 16; m; m >>= 1) sum += __shfl_xor_sync(0xffffffffu, sum, m);
        if (l == 0) ssum[wid] = sum;
        __syncthreads();
        if (tid < 128)
            atomicMax(&g_rowmax[bi * TILE + tid], srm_bi[tid]);
        else if (tid < 192)
            atomicMax(&g_rowmax[bj * TILE + h * 64 + (tid - 128)], srm_bjH[tid - 128]);
        if (tid == 0) {
            float t = 0.f;
#pragma unroll
            for (int ww = 0; ww < 8; ww++) t += ssum[ww];
            g_partial[w] = t;
        }
        w = wn_next;
    }

    // ---- CTA done; last CTA finalizes ----
    __threadfence();
    __shared__ unsigned int s_last;
    if (tid == 0) s_last = (atomicAdd(&g_done, 1u) == (unsigned)(gridDim.x - 1)) ? 1u : 0u;
    __syncthreads();
    if (!s_last) return;
    __threadfence();

    double smax = 0.0, ssumd = 0.0;
    for (int i = tid; i < n; i += 256) {
        smax += (double)__uint_as_float(g_rowmax[i]);
        g_rowmax[i] = 0u;
    }
    for (int i = tid; i < nwork; i += 256) ssumd += (double)g_partial[i];
#pragma unroll
    for (int m = 16; m; m >>= 1) {
        smax  += __shfl_xor_sync(0xffffffffu, smax, m);
        ssumd += __shfl_xor_sync(0xffffffffu, ssumd, m);
    }
    __shared__ double d1[8], d2[8];
    if (l == 0) { d1[wid] = smax; d2[wid] = ssumd; }
    __syncthreads();
    if (tid == 0) {
        double t1 = 0.0, t2 = 0.0;
#pragma unroll
        for (int ww = 0; ww < 8; ww++) { t1 += d1[ww]; t2 += d2[ww]; }
        out[0] = (float)(t1 / (double)n);
        out[1] = (float)(t2 / (2.0 * (double)n * (double)(n - 1)));
        g_work = 0u;
        g_done = 0u;
    }
}

extern "C" void kernel_launch(void* const* d_in, const int* in_sizes, int n_in,
                              void* d_out, int out_size) {
    const float* p1 = (const float*)d_in[0];
    const float* p2 = (const float*)d_in[1];
    float* out = (float*)d_out;
    const int n = in_sizes[0] / DIM;            // 4096
    const int nt = n / TILE;                    // 32
    const int nwork = nt * (nt + 1);            // 1056 half-pairs

    int nsm = 148;
    cudaDeviceGetAttribute(&nsm, cudaDevAttrMultiProcessorCount, 0);

    cudaFuncSetAttribute(triplet_persist_kernel,
                         cudaFuncAttributeMaxDynamicSharedMemorySize, SMEM_TOTAL);

    prep_kernel<<<n / 8, 256>>>(p1, p2, n);
    triplet_persist_kernel<<<nsm * 2, 256, SMEM_TOTAL>>>(out, n, nt, nwork);
}

// round 12
// speedup vs baseline: 1.3143x; 1.3143x over previous
#include <cuda_runtime.h>
#include <cuda_fp16.h>
#include <cstdint>

#define MARGIN 0.3f
#define DIM  128
#define TILE 128
#define MAXN 4096
#define MAXT (MAXN / TILE)
#define MAXPAIR (MAXT * (MAXT + 1) / 2)
#define CT   16384                 // image chunk tile: 128 rows x 64 fp16 cols (SW128)

// ---- dynamic smem layout (bytes) ----
#define SM_CBI   0                 // 128 f
#define SM_N1BI  512
#define SM_N2BI  1024
#define SM_CBJH  1536              // 64 f
#define SM_N1BJH 1792
#define SM_N2BJH 2048
#define SM_RMI   2304              // 128 u
#define SM_RMJH  2816              // 64 u
#define SM_SSUM  3072              // 8 f
#define SM_OPS   4096              // 64KB operand region, 1024-aligned
#define SMEM_TOTAL (SM_OPS + 64 * 1024)

// phase1 (all prefetched, hi only): A [0,32K) (c0,c1); B1 [32K,48K) (c0,c1); B2 [48K,64K)
#define P1_AH  0
#define P1_B1H (32 * 1024)
#define P1_B2H (48 * 1024)
// phase2 double buffer (reuses region after phase1 reads done): A2H 8K + B2H 16K = 24K each
#define P2_BUF(c) ((c) * 24 * 1024)
#define P2_A2H 0
#define P2_B2H (8 * 1024)

__device__ float g_n1[MAXN], g_n2[MAXN], g_C[MAXN];
__device__ unsigned int g_rowmax[MAXN];      // zero at load; finalizer re-zeros
__device__ float g_partial[2 * MAXPAIR];
__device__ unsigned int g_work;              // work ticket; finalizer re-zeros
__device__ unsigned int g_done;              // CTA done counter; finalizer re-zeros

// pre-swizzled fp16 hi images: [tile][chunk][16KB]
__device__ __align__(16) unsigned char g_img_p1h[MAXT * 2 * CT];
__device__ __align__(16) unsigned char g_img_p2h[MAXT * 2 * CT];

__device__ __forceinline__ uint32_t smem_u32(const void* p) {
    uint32_t a;
    asm("{ .reg .u64 t; cvta.to.shared.u64 t, %1; cvt.u32.u64 %0, t; }" : "=r"(a) : "l"(p));
    return a;
}
__device__ __forceinline__ int swz(int row, int kc) {
    int b = row * 128 + kc * 2;
    return b ^ ((b >> 3) & 0x70);
}
__device__ __forceinline__ uint32_t taddrA(uint32_t base0, int row, int kcol) {
    return base0 + ((kcol >> 6) << 14) + swz(row, kcol & 63);
}
__device__ __forceinline__ void ldsm4(uint32_t addr, uint32_t r[4]) {
    asm volatile("ldmatrix.sync.aligned.m8n8.x4.shared.b16 {%0,%1,%2,%3}, [%4];"
                 : "=r"(r[0]), "=r"(r[1]), "=r"(r[2]), "=r"(r[3]) : "r"(addr));
}
__device__ __forceinline__ void cp16(uint32_t saddr, const void* g) {
    asm volatile("cp.async.cg.shared.global [%0], [%1], 16;" :: "r"(saddr), "l"(g));
}
#define CP_COMMIT() asm volatile("cp.async.commit_group;" ::: "memory")
#define CP_WAIT0()  asm volatile("cp.async.wait_group 0;" ::: "memory")
#define CP_WAIT1()  asm volatile("cp.async.wait_group 1;" ::: "memory")

#define MMA(d, a, b)                                                               \
    asm volatile("mma.sync.aligned.m16n8k16.row.col.f32.f16.f16.f32 "              \
                 "{%0,%1,%2,%3},{%4,%5,%6,%7},{%8,%9},{%0,%1,%2,%3};"              \
                 : "+f"((d)[0]), "+f"((d)[1]), "+f"((d)[2]), "+f"((d)[3])          \
                 : "r"((a)[0]), "r"((a)[1]), "r"((a)[2]), "r"((a)[3]),             \
                   "r"((b)[0]), "r"((b)[1]))

union HU { __half2 h; uint32_t u; };

__device__ __forceinline__ void cpa(uint32_t sdst, const unsigned char* gsrc, int bytes, int tid) {
    for (int t = tid * 16; t < bytes; t += 4096) cp16(sdst + t, gsrc + t);
}

__device__ __forceinline__ void decode(int w, int nt, int& bi, int& bj, int& h) {
    int pairid = w >> 1;
    h = w & 1;
    bi = 0;
    int rem = pairid;
    while (rem >= nt - bi) { rem -= (nt - bi); bi++; }
    bj = bi + rem;
}

// phase1 prologue: g0 = A both chunks + B1 both chunks (48K); g1 = B2 both chunks (16K)
__device__ __forceinline__ void load_item(uint32_t OPS, int bi, int bj, int h, int tid) {
    size_t b0 = (size_t)(bj * 2 + 0) * CT + h * 8192;
    size_t b1 = (size_t)(bj * 2 + 1) * CT + h * 8192;
    cpa(OPS + P1_AH, g_img_p1h + (size_t)(bi * 2) * CT, 2 * CT, tid);
    cpa(OPS + P1_B1H,        g_img_p1h + b0, 8192, tid);
    cpa(OPS + P1_B1H + 8192, g_img_p1h + b1, 8192, tid);
    CP_COMMIT();                                                   // g0
    cpa(OPS + P1_B2H,        g_img_p2h + b0, 8192, tid);
    cpa(OPS + P1_B2H + 8192, g_img_p2h + b1, 8192, tid);
    CP_COMMIT();                                                   // g1
}

// 4 ksteps of one gram, hi-only: 6 ldsm -> 8 MMA per kstep
__device__ __forceinline__ void group4(
    uint32_t AH, uint32_t BH, int kAbase,
    int arow, int akoff, int brow, int bkoff, float (&acc)[2][4][4])
{
#pragma unroll
    for (int ks = 0; ks < 4; ks++) {
        const int kA = kAbase + ks * 16;
        const int kB = ks * 16;
        uint32_t ah[2][4];
#pragma unroll
        for (int mf = 0; mf < 2; mf++)
            ldsm4(taddrA(AH, arow + mf * 16, kA + akoff), ah[mf]);
        uint32_t bh[4][2];
#pragma unroll
        for (int np = 0; np < 2; np++) {
            uint32_t t4[4];
            ldsm4(BH + swz(brow + np * 16, kB + bkoff), t4);
            bh[2*np][0]=t4[0]; bh[2*np][1]=t4[1]; bh[2*np+1][0]=t4[2]; bh[2*np+1][1]=t4[3];
        }
#pragma unroll
        for (int mf = 0; mf < 2; mf++)
#pragma unroll
            for (int nf = 0; nf < 4; nf++)
                MMA(acc[mf][nf], ah[mf], bh[nf]);
    }
}

__device__ __forceinline__ void epi_normal(
    float (&acc)[2][4][4], const float* Crow, const float* ncol,
    int wm, int wn, int qr, int qc, int l, bool dz, int rbase, int cbase,
    unsigned int* srm, float& sum)
{
    float Cr[2][2], nc[4][2];
#pragma unroll
    for (int mf = 0; mf < 2; mf++) {
        int r0 = wm * 32 + mf * 16 + qr;
        Cr[mf][0] = Crow[r0]; Cr[mf][1] = Crow[r0 + 8];
    }
#pragma unroll
    for (int nf = 0; nf < 4; nf++) {
        int c0 = wn * 32 + nf * 8 + qc;
        nc[nf][0] = ncol[c0]; nc[nf][1] = ncol[c0 + 1];
    }
    float rmax[2][2] = {{0.f, 0.f}, {0.f, 0.f}};
#pragma unroll
    for (int mf = 0; mf < 2; mf++)
#pragma unroll
        for (int nf = 0; nf < 4; nf++)
#pragma unroll
            for (int e = 0; e < 4; e++) {
                int rr = e >> 1, cc = e & 1;
                float v = fmaxf(Cr[mf][rr] - nc[nf][cc] + 2.f * acc[mf][nf][e], 0.f);
                if (dz) {
                    int rl = rbase + wm * 32 + mf * 16 + qr + rr * 8;
                    int cl = cbase + wn * 32 + nf * 8 + qc + cc;
                    if (rl == cl) v = 0.f;
                }
                sum += v;
                rmax[mf][rr] = fmaxf(rmax[mf][rr], v);
            }
#pragma unroll
    for (int m = 1; m <= 2; m <<= 1)
#pragma unroll
        for (int mf = 0; mf < 2; mf++) {
            rmax[mf][0] = fmaxf(rmax[mf][0], __shfl_xor_sync(0xffffffffu, rmax[mf][0], m));
            rmax[mf][1] = fmaxf(rmax[mf][1], __shfl_xor_sync(0xffffffffu, rmax[mf][1], m));
        }
    if ((l & 3) == 0) {
#pragma unroll
        for (int mf = 0; mf < 2; mf++) {
            atomicMax(&srm[wm * 32 + mf * 16 + qr],     __float_as_uint(rmax[mf][0]));
            atomicMax(&srm[wm * 32 + mf * 16 + qr + 8], __float_as_uint(rmax[mf][1]));
        }
    }
}

__device__ __forceinline__ void epi_trans(
    float (&acc)[2][4][4], const float* Ccol, const float* nrow,
    int wm, int wn, int qr, int qc, int l,
    unsigned int* srm, float& sum)
{
    float Ct[4][2], nr[2][2];
#pragma unroll
    for (int nf = 0; nf < 4; nf++) {
        int c0 = wn * 32 + nf * 8 + qc;
        Ct[nf][0] = Ccol[c0]; Ct[nf][1] = Ccol[c0 + 1];
    }
#pragma unroll
    for (int mf = 0; mf < 2; mf++) {
        int r0 = wm * 32 + mf * 16 + qr;
        nr[mf][0] = nrow[r0]; nr[mf][1] = nrow[r0 + 8];
    }
    float cmax[4][2] = {{0.f,0.f},{0.f,0.f},{0.f,0.f},{0.f,0.f}};
#pragma unroll
    for (int mf = 0; mf < 2; mf++)
#pragma unroll
        for (int nf = 0; nf < 4; nf++)
#pragma unroll
            for (int e = 0; e < 4; e++) {
                int rr = e >> 1, cc = e & 1;
                float v = fmaxf(Ct[nf][cc] - nr[mf][rr] + 2.f * acc[mf][nf][e], 0.f);
                sum += v;
                cmax[nf][cc] = fmaxf(cmax[nf][cc], v);
            }
#pragma unroll
    for (int m = 4; m <= 16; m <<= 1)
#pragma unroll
        for (int nf = 0; nf < 4; nf++) {
            cmax[nf][0] = fmaxf(cmax[nf][0], __shfl_xor_sync(0xffffffffu, cmax[nf][0], m));
            cmax[nf][1] = fmaxf(cmax[nf][1], __shfl_xor_sync(0xffffffffu, cmax[nf][1], m));
        }
    if (l < 4) {
#pragma unroll
        for (int nf = 0; nf < 4; nf++) {
            int c0 = wn * 32 + nf * 8 + qc;
            atomicMax(&srm[c0],     __float_as_uint(cmax[nf][0]));
            atomicMax(&srm[c0 + 1], __float_as_uint(cmax[nf][1]));
        }
    }
}

// ---- prep: norms/C + pre-swizzled fp16 hi images ----
__global__ void __launch_bounds__(256)
prep_kernel(const float* __restrict__ p1, const float* __restrict__ p2, int n) {
    int row = blockIdx.x * 8 + (threadIdx.x >> 5);
    int lane = threadIdx.x & 31;
    if (row >= n) return;
    float4 a = ((const float4*)(p1 + (size_t)row * DIM))[lane];
    float4 b = ((const float4*)(p2 + (size_t)row * DIM))[lane];

    float n1 = a.x*a.x + a.y*a.y + a.z*a.z + a.w*a.w;
    float n2 = b.x*b.x + b.y*b.y + b.z*b.z + b.w*b.w;
    float dx = a.x-b.x, dy = a.y-b.y, dz = a.z-b.z, dw = a.w-b.w;
    float dap = dx*dx + dy*dy + dz*dz + dw*dw;
#pragma unroll
    for (int m = 16; m; m >>= 1) {
        n1 += __shfl_xor_sync(0xffffffffu, n1, m);
        n2 += __shfl_xor_sync(0xffffffffu, n2, m);
        dap += __shfl_xor_sync(0xffffffffu, dap, m);
    }
    if (lane == 0) {
        g_n1[row] = n1; g_n2[row] = n2; g_C[row] = dap - n1 + MARGIN;
    }

    int tile = row >> 7, lr = row & 127;
    int c4 = lane * 4, chunk = c4 >> 6, lc = c4 & 63;
    size_t off = (size_t)(tile * 2 + chunk) * CT + swz(lr, lc);

    HU h0, h1;
    h0.h = __floats2half2_rn(a.x, a.y);
    h1.h = __floats2half2_rn(a.z, a.w);
    *(uint2*)(g_img_p1h + off) = make_uint2(h0.u, h1.u);
    h0.h = __floats2half2_rn(b.x, b.y);
    h1.h = __floats2half2_rn(b.z, b.w);
    *(uint2*)(g_img_p2h + off) = make_uint2(h0.u, h1.u);
}

// ---- main: persistent CTAs, fully-prefetched hi-only phase1 ----
__global__ void __launch_bounds__(256, 2)
triplet_persist_kernel(float* __restrict__ out, int n, int nt, int nwork) {
    extern __shared__ char smem[];
    const uint32_t sbase = smem_u32(smem);
    const int tid = threadIdx.x;
    const int wid = tid >> 5;
    const int l   = tid & 31;

    float* sCbi   = (float*)(smem + SM_CBI);
    float* sn1bi  = (float*)(smem + SM_N1BI);
    float* sn2bi  = (float*)(smem + SM_N2BI);
    float* sCbjH  = (float*)(smem + SM_CBJH);
    float* sn1bjH = (float*)(smem + SM_N1BJH);
    float* sn2bjH = (float*)(smem + SM_N2BJH);
    unsigned int* srm_bi  = (unsigned int*)(smem + SM_RMI);
    unsigned int* srm_bjH = (unsigned int*)(smem + SM_RMJH);
    float* ssum = (float*)(smem + SM_SSUM);
    const uint32_t OPS = sbase + SM_OPS;

    __shared__ int s_w;

    const int wm = wid & 3;
    const int wn = wid >> 2;
    const int qr = l >> 2;
    const int qc = (l & 3) * 2;
    const int arow = wm * 32 + (l & 7) + ((l >> 3) & 1) * 8;
    const int akoff = (l >> 4) * 8;
    const int brow = wn * 32 + (l & 7) + ((l >> 4) << 3);
    const int bkoff = ((l >> 3) & 1) * 8;
    const int wm2 = wid & 1;
    const int wn2 = wid >> 1;
    const int arow2 = wm2 * 32 + (l & 7) + ((l >> 3) & 1) * 8;
    const int brow2 = wn2 * 32 + (l & 7) + ((l >> 4) << 3);

    if (tid == 0) s_w = (int)atomicAdd(&g_work, 1u);
    __syncthreads();
    int w = s_w;
    if (w < nwork) {
        int bi, bj, h; decode(w, nt, bi, bj, h);
        load_item(OPS, bi, bj, h, tid);                 // g0, g1 outstanding
    }

    while (w < nwork) {
        int bi, bj, h; decode(w, nt, bi, bj, h);
        const bool diag = (bi == bj);

        __syncthreads();
        if (tid < 128) {
            srm_bi[tid] = 0u;
            sCbi[tid]  = g_C[bi * TILE + tid];
            sn1bi[tid] = g_n1[bi * TILE + tid];
            sn2bi[tid] = g_n2[bi * TILE + tid];
        } else if (tid < 192) {
            int t = tid - 128;
            srm_bjH[t] = 0u;
            sCbjH[t]  = g_C[bj * TILE + h * 64 + t];
            sn1bjH[t] = g_n1[bj * TILE + h * 64 + t];
            sn2bjH[t] = g_n2[bj * TILE + h * 64 + t];
        } else if (tid == 255) {
            s_w = (int)atomicAdd(&g_work, 1u);          // ticket for NEXT item
        }

        float sum = 0.f;
        float acc1[2][4][4], acc2[2][4][4];
#pragma unroll
        for (int mf = 0; mf < 2; mf++)
#pragma unroll
            for (int nf = 0; nf < 4; nf++)
#pragma unroll
                for (int e = 0; e < 4; e++) { acc1[mf][nf][e] = 0.f; acc2[mf][nf][e] = 0.f; }

        CP_WAIT1();             // g0 (A + B1) ready
        __syncthreads();        // publishes s_w too
        const int wn_next = s_w;

        // ---- phase1: acc1 over full K (B2 load still in flight under it) ----
        group4(OPS + P1_AH, OPS + P1_B1H,        0,  arow, akoff, brow, bkoff, acc1);
        group4(OPS + P1_AH, OPS + P1_B1H + 8192, 64, arow, akoff, brow, bkoff, acc1);
        CP_WAIT0();             // g1 (B2) ready
        __syncthreads();
        group4(OPS + P1_AH, OPS + P1_B2H,        0,  arow, akoff, brow, bkoff, acc2);
        group4(OPS + P1_AH, OPS + P1_B2H + 8192, 64, arow, akoff, brow, bkoff, acc2);
        __syncthreads();        // all phase1 operand reads done

        if (diag) {
            if (wn_next < nwork) {
                int nbi, nbj, nh; decode(wn_next, nt, nbi, nbj, nh);
                load_item(OPS, nbi, nbj, nh, tid);
            }
            epi_normal(acc1, sCbi, sn1bjH, wm, wn, qr, qc, l, true,
                       bi * TILE, bj * TILE + h * 64, srm_bi, sum);
            epi_normal(acc2, sCbi, sn2bjH, wm, wn, qr, qc, l, true,
                       bi * TILE, bj * TILE + h * 64, srm_bi, sum);
        } else {
            const size_t hoff0 = (size_t)(bj * 2 + 0) * CT + h * 8192;
            const size_t hoff1 = (size_t)(bj * 2 + 1) * CT + h * 8192;
            // phase2 buf0 prefetch (overwrites phase1 A region; reads done)
            cpa(OPS + P2_BUF(0) + P2_A2H, g_img_p1h + hoff0, 8192, tid);
            cpa(OPS + P2_BUF(0) + P2_B2H, g_img_p2h + (size_t)(bi * 2 + 0) * CT, CT, tid);
            CP_COMMIT();

            epi_normal(acc1, sCbi, sn1bjH, wm, wn, qr, qc, l, false,
                       bi * TILE, bj * TILE + h * 64, srm_bi, sum);
            epi_trans(acc1, sCbjH, sn1bi, wm, wn, qr, qc, l, srm_bjH, sum);
            epi_normal(acc2, sCbi, sn2bjH, wm, wn, qr, qc, l, false,
                       bi * TILE, bj * TILE + h * 64, srm_bi, sum);

            float accb[2][4][4];
#pragma unroll
            for (int mf = 0; mf < 2; mf++)
#pragma unroll
                for (int nf = 0; nf < 4; nf++)
#pragma unroll
                    for (int e = 0; e < 4; e++) accb[mf][nf][e] = 0.f;

            CP_WAIT0();
            __syncthreads();
            cpa(OPS + P2_BUF(1) + P2_A2H, g_img_p1h + hoff1, 8192, tid);
            cpa(OPS + P2_BUF(1) + P2_B2H, g_img_p2h + (size_t)(bi * 2 + 1) * CT, CT, tid);
            CP_COMMIT();

            group4(OPS + P2_BUF(0) + P2_A2H, OPS + P2_BUF(0) + P2_B2H, 0,
                   arow2, akoff, brow2, bkoff, accb);
            CP_WAIT0();
            __syncthreads();
            group4(OPS + P2_BUF(1) + P2_A2H, OPS + P2_BUF(1) + P2_B2H, 0,
                   arow2, akoff, brow2, bkoff, accb);
            __syncthreads();    // all phase2 operand reads done

            if (wn_next < nwork) {
                int nbi, nbj, nh; decode(wn_next, nt, nbi, nbj, nh);
                load_item(OPS, nbi, nbj, nh, tid);
            }
            epi_normal(accb, sCbjH, sn2bi, wm2, wn2, qr, qc, l, false, 0, 0, srm_bjH, sum);
        }

        // ---- publish this item ----
#pragma unroll
        for (int m = 16; m; m >>= 1) sum += __shfl_xor_sync(0xffffffffu, sum, m);
        if (l == 0) ssum[wid] = sum;
        __syncthreads();
        if (tid < 128)
            atomicMax(&g_rowmax[bi * TILE + tid], srm_bi[tid]);
        else if (tid < 192)
            atomicMax(&g_rowmax[bj * TILE + h * 64 + (tid - 128)], srm_bjH[tid - 128]);
        if (tid == 0) {
            float t = 0.f;
#pragma unroll
            for (int ww = 0; ww < 8; ww++) t += ssum[ww];
            g_partial[w] = t;
        }
        w = wn_next;
    }

    // ---- CTA done; last CTA finalizes ----
    __threadfence();
    __shared__ unsigned int s_last;
    if (tid == 0) s_last = (atomicAdd(&g_done, 1u) == (unsigned)(gridDim.x - 1)) ? 1u : 0u;
    __syncthreads();
    if (!s_last) return;
    __threadfence();

    double smax = 0.0, ssumd = 0.0;
    for (int i = tid; i < n; i += 256) {
        smax += (double)__uint_as_float(g_rowmax[i]);
        g_rowmax[i] = 0u;
    }
    for (int i = tid; i < nwork; i += 256) ssumd += (double)g_partial[i];
#pragma unroll
    for (int m = 16; m; m >>= 1) {
        smax  += __shfl_xor_sync(0xffffffffu, smax, m);
        ssumd += __shfl_xor_sync(0xffffffffu, ssumd, m);
    }
    __shared__ double d1[8], d2[8];
    if (l == 0) { d1[wid] = smax; d2[wid] = ssumd; }
    __syncthreads();
    if (tid == 0) {
        double t1 = 0.0, t2 = 0.0;
#pragma unroll
        for (int ww = 0; ww < 8; ww++) { t1 += d1[ww]; t2 += d2[ww]; }
        out[0] = (float)(t1 / (double)n);
        out[1] = (float)(t2 / (2.0 * (double)n * (double)(n - 1)));
        g_work = 0u;
        g_done = 0u;
    }
}

extern "C" void kernel_launch(void* const* d_in, const int* in_sizes, int n_in,
                              void* d_out, int out_size) {
    const float* p1 = (const float*)d_in[0];
    const float* p2 = (const float*)d_in[1];
    float* out = (float*)d_out;
    const int n = in_sizes[0] / DIM;            // 4096
    const int nt = n / TILE;                    // 32
    const int nwork = nt * (nt + 1);            // 1056 half-pairs

    int nsm = 148;
    cudaDeviceGetAttribute(&nsm, cudaDevAttrMultiProcessorCount, 0);

    cudaFuncSetAttribute(triplet_persist_kernel,
                         cudaFuncAttributeMaxDynamicSharedMemorySize, SMEM_TOTAL);

    prep_kernel<<<n / 8, 256>>>(p1, p2, n);
    triplet_persist_kernel<<<nsm * 2, 256, SMEM_TOTAL>>>(out, n, nt, nwork);
}

// round 13
// speedup vs baseline: 1.3799x; 1.0499x over previous
#include <cuda_runtime.h>
#include <cuda_fp16.h>
#include <cstdint>

#define MARGIN 0.3f
#define DIM  128
#define TILE 128
#define MAXN 4096
#define MAXT (MAXN / TILE)
#define MAXPAIR (MAXT * (MAXT + 1) / 2)
#define CT   16384                 // image chunk tile: 128 rows x 64 fp16 cols (SW128)

// ---- dynamic smem layout (bytes) ----
#define SM_CBI   0                 // 128 f
#define SM_N1BI  512
#define SM_N2BI  1024
#define SM_CBJH  1536              // 64 f
#define SM_N1BJH 1792
#define SM_N2BJH 2048
#define SM_RMI   2304              // 128 u
#define SM_RMJH  2816              // 64 u
#define SM_SSUM  3072              // 8 f
#define SM_OPS   4096              // 64KB operand region, 1024-aligned
#define SMEM_TOTAL (SM_OPS + 64 * 1024)

// phase1 (all prefetched, hi only): A [0,32K) (c0,c1); B1 [32K,48K); B2 [48K,64K)
#define P1_AH  0
#define P1_B1H (32 * 1024)
#define P1_B2H (48 * 1024)
// phase2 double buffer (reuses region after phase1 reads done): A2H 8K + B2H 16K = 24K each
#define P2_BUF(c) ((c) * 24 * 1024)
#define P2_A2H 0
#define P2_B2H (8 * 1024)

__device__ float g_n1[MAXN], g_n2[MAXN], g_C[MAXN];
__device__ unsigned int g_rowmax[MAXN];      // zero at load; finalizer re-zeros
__device__ float g_partial[2 * MAXPAIR];
__device__ unsigned int g_work;              // work ticket; finalizer re-zeros
__device__ unsigned int g_done;              // CTA done counter; finalizer re-zeros

// pre-swizzled fp16 hi images: [tile][chunk][16KB]
__device__ __align__(16) unsigned char g_img_p1h[MAXT * 2 * CT];
__device__ __align__(16) unsigned char g_img_p2h[MAXT * 2 * CT];

__device__ __forceinline__ uint32_t smem_u32(const void* p) {
    uint32_t a;
    asm("{ .reg .u64 t; cvta.to.shared.u64 t, %1; cvt.u32.u64 %0, t; }" : "=r"(a) : "l"(p));
    return a;
}
__device__ __forceinline__ int swz(int row, int kc) {
    int b = row * 128 + kc * 2;
    return b ^ ((b >> 3) & 0x70);
}
__device__ __forceinline__ uint32_t taddrA(uint32_t base0, int row, int kcol) {
    return base0 + ((kcol >> 6) << 14) + swz(row, kcol & 63);
}
__device__ __forceinline__ void ldsm4(uint32_t addr, uint32_t r[4]) {
    asm volatile("ldmatrix.sync.aligned.m8n8.x4.shared.b16 {%0,%1,%2,%3}, [%4];"
                 : "=r"(r[0]), "=r"(r[1]), "=r"(r[2]), "=r"(r[3]) : "r"(addr));
}
__device__ __forceinline__ void cp16(uint32_t saddr, const void* g) {
    asm volatile("cp.async.cg.shared.global [%0], [%1], 16;" :: "r"(saddr), "l"(g));
}
#define CP_COMMIT() asm volatile("cp.async.commit_group;" ::: "memory")
#define CP_WAIT0()  asm volatile("cp.async.wait_group 0;" ::: "memory")
#define CP_WAIT1()  asm volatile("cp.async.wait_group 1;" ::: "memory")

#define MMA(d, a, b)                                                               \
    asm volatile("mma.sync.aligned.m16n8k16.row.col.f32.f16.f16.f32 "              \
                 "{%0,%1,%2,%3},{%4,%5,%6,%7},{%8,%9},{%0,%1,%2,%3};"              \
                 : "+f"((d)[0]), "+f"((d)[1]), "+f"((d)[2]), "+f"((d)[3])          \
                 : "r"((a)[0]), "r"((a)[1]), "r"((a)[2]), "r"((a)[3]),             \
                   "r"((b)[0]), "r"((b)[1]))

union HU { __half2 h; uint32_t u; };

__device__ __forceinline__ void cpa(uint32_t sdst, const unsigned char* gsrc, int bytes, int tid) {
    for (int t = tid * 16; t < bytes; t += 4096) cp16(sdst + t, gsrc + t);
}

__device__ __forceinline__ void decode(int w, int nt, int& bi, int& bj, int& h) {
    int pairid = w >> 1;
    h = w & 1;
    bi = 0;
    int rem = pairid;
    while (rem >= nt - bi) { rem -= (nt - bi); bi++; }
    bj = bi + rem;
}

// phase1 prologue: g0 = A both chunks + B1 both chunks (48K); g1 = B2 both chunks (16K)
__device__ __forceinline__ void load_item(uint32_t OPS, int bi, int bj, int h, int tid) {
    size_t b0 = (size_t)(bj * 2 + 0) * CT + h * 8192;
    size_t b1 = (size_t)(bj * 2 + 1) * CT + h * 8192;
    cpa(OPS + P1_AH, g_img_p1h + (size_t)(bi * 2) * CT, 2 * CT, tid);
    cpa(OPS + P1_B1H,        g_img_p1h + b0, 8192, tid);
    cpa(OPS + P1_B1H + 8192, g_img_p1h + b1, 8192, tid);
    CP_COMMIT();                                                   // g0
    cpa(OPS + P1_B2H,        g_img_p2h + b0, 8192, tid);
    cpa(OPS + P1_B2H + 8192, g_img_p2h + b1, 8192, tid);
    CP_COMMIT();                                                   // g1
}

// 4 ksteps of one gram, hi-only: 4 ldsm.x4 -> 8 MMA per kstep
__device__ __forceinline__ void group4(
    uint32_t AH, uint32_t BH, int kAbase,
    int arow, int akoff, int brow, int bkoff, float (&acc)[2][4][4])
{
#pragma unroll
    for (int ks = 0; ks < 4; ks++) {
        const int kA = kAbase + ks * 16;
        const int kB = ks * 16;
        uint32_t ah[2][4];
#pragma unroll
        for (int mf = 0; mf < 2; mf++)
            ldsm4(taddrA(AH, arow + mf * 16, kA + akoff), ah[mf]);
        uint32_t bh[4][2];
#pragma unroll
        for (int np = 0; np < 2; np++) {
            uint32_t t4[4];
            ldsm4(BH + swz(brow + np * 16, kB + bkoff), t4);
            bh[2*np][0]=t4[0]; bh[2*np][1]=t4[1]; bh[2*np+1][0]=t4[2]; bh[2*np+1][1]=t4[3];
        }
#pragma unroll
        for (int mf = 0; mf < 2; mf++)
#pragma unroll
            for (int nf = 0; nf < 4; nf++)
                MMA(acc[mf][nf], ah[mf], bh[nf]);
    }
}

__device__ __forceinline__ void epi_normal(
    float (&acc)[2][4][4], const float* Crow, const float* ncol,
    int wm, int wn, int qr, int qc, int l, bool dz, int rbase, int cbase,
    unsigned int* srm, float& sum)
{
    float Cr[2][2], nc[4][2];
#pragma unroll
    for (int mf = 0; mf < 2; mf++) {
        int r0 = wm * 32 + mf * 16 + qr;
        Cr[mf][0] = Crow[r0]; Cr[mf][1] = Crow[r0 + 8];
    }
#pragma unroll
    for (int nf = 0; nf < 4; nf++) {
        int c0 = wn * 32 + nf * 8 + qc;
        nc[nf][0] = ncol[c0]; nc[nf][1] = ncol[c0 + 1];
    }
    float rmax[2][2] = {{0.f, 0.f}, {0.f, 0.f}};
#pragma unroll
    for (int mf = 0; mf < 2; mf++)
#pragma unroll
        for (int nf = 0; nf < 4; nf++)
#pragma unroll
            for (int e = 0; e < 4; e++) {
                int rr = e >> 1, cc = e & 1;
                float v = fmaxf(Cr[mf][rr] - nc[nf][cc] + 2.f * acc[mf][nf][e], 0.f);
                if (dz) {
                    int rl = rbase + wm * 32 + mf * 16 + qr + rr * 8;
                    int cl = cbase + wn * 32 + nf * 8 + qc + cc;
                    if (rl == cl) v = 0.f;
                }
                sum += v;
                rmax[mf][rr] = fmaxf(rmax[mf][rr], v);
            }
#pragma unroll
    for (int m = 1; m <= 2; m <<= 1)
#pragma unroll
        for (int mf = 0; mf < 2; mf++) {
            rmax[mf][0] = fmaxf(rmax[mf][0], __shfl_xor_sync(0xffffffffu, rmax[mf][0], m));
            rmax[mf][1] = fmaxf(rmax[mf][1], __shfl_xor_sync(0xffffffffu, rmax[mf][1], m));
        }
    if ((l & 3) == 0) {
#pragma unroll
        for (int mf = 0; mf < 2; mf++) {
            atomicMax(&srm[wm * 32 + mf * 16 + qr],     __float_as_uint(rmax[mf][0]));
            atomicMax(&srm[wm * 32 + mf * 16 + qr + 8], __float_as_uint(rmax[mf][1]));
        }
    }
}

__device__ __forceinline__ void epi_trans(
    float (&acc)[2][4][4], const float* Ccol, const float* nrow,
    int wm, int wn, int qr, int qc, int l,
    unsigned int* srm, float& sum)
{
    float Ct[4][2], nr[2][2];
#pragma unroll
    for (int nf = 0; nf < 4; nf++) {
        int c0 = wn * 32 + nf * 8 + qc;
        Ct[nf][0] = Ccol[c0]; Ct[nf][1] = Ccol[c0 + 1];
    }
#pragma unroll
    for (int mf = 0; mf < 2; mf++) {
        int r0 = wm * 32 + mf * 16 + qr;
        nr[mf][0] = nrow[r0]; nr[mf][1] = nrow[r0 + 8];
    }
    float cmax[4][2] = {{0.f,0.f},{0.f,0.f},{0.f,0.f},{0.f,0.f}};
#pragma unroll
    for (int mf = 0; mf < 2; mf++)
#pragma unroll
        for (int nf = 0; nf < 4; nf++)
#pragma unroll
            for (int e = 0; e < 4; e++) {
                int rr = e >> 1, cc = e & 1;
                float v = fmaxf(Ct[nf][cc] - nr[mf][rr] + 2.f * acc[mf][nf][e], 0.f);
                sum += v;
                cmax[nf][cc] = fmaxf(cmax[nf][cc], v);
            }
#pragma unroll
    for (int m = 4; m <= 16; m <<= 1)
#pragma unroll
        for (int nf = 0; nf < 4; nf++) {
            cmax[nf][0] = fmaxf(cmax[nf][0], __shfl_xor_sync(0xffffffffu, cmax[nf][0], m));
            cmax[nf][1] = fmaxf(cmax[nf][1], __shfl_xor_sync(0xffffffffu, cmax[nf][1], m));
        }
    if (l < 4) {
#pragma unroll
        for (int nf = 0; nf < 4; nf++) {
            int c0 = wn * 32 + nf * 8 + qc;
            atomicMax(&srm[c0],     __float_as_uint(cmax[nf][0]));
            atomicMax(&srm[c0 + 1], __float_as_uint(cmax[nf][1]));
        }
    }
}

// ---- prep: norms/C + pre-swizzled fp16 hi images ----
__global__ void __launch_bounds__(256)
prep_kernel(const float* __restrict__ p1, const float* __restrict__ p2, int n) {
    int row = blockIdx.x * 8 + (threadIdx.x >> 5);
    int lane = threadIdx.x & 31;
    if (row >= n) return;
    float4 a = ((const float4*)(p1 + (size_t)row * DIM))[lane];
    float4 b = ((const float4*)(p2 + (size_t)row * DIM))[lane];

    float n1 = a.x*a.x + a.y*a.y + a.z*a.z + a.w*a.w;
    float n2 = b.x*b.x + b.y*b.y + b.z*b.z + b.w*b.w;
    float dx = a.x-b.x, dy = a.y-b.y, dz = a.z-b.z, dw = a.w-b.w;
    float dap = dx*dx + dy*dy + dz*dz + dw*dw;
#pragma unroll
    for (int m = 16; m; m >>= 1) {
        n1 += __shfl_xor_sync(0xffffffffu, n1, m);
        n2 += __shfl_xor_sync(0xffffffffu, n2, m);
        dap += __shfl_xor_sync(0xffffffffu, dap, m);
    }
    if (lane == 0) {
        g_n1[row] = n1; g_n2[row] = n2; g_C[row] = dap - n1 + MARGIN;
    }

    int tile = row >> 7, lr = row & 127;
    int c4 = lane * 4, chunk = c4 >> 6, lc = c4 & 63;
    size_t off = (size_t)(tile * 2 + chunk) * CT + swz(lr, lc);

    HU h0, h1;
    h0.h = __floats2half2_rn(a.x, a.y);
    h1.h = __floats2half2_rn(a.z, a.w);
    *(uint2*)(g_img_p1h + off) = make_uint2(h0.u, h1.u);
    h0.h = __floats2half2_rn(b.x, b.y);
    h1.h = __floats2half2_rn(b.z, b.w);
    *(uint2*)(g_img_p2h + off) = make_uint2(h0.u, h1.u);
}

// ---- main: persistent CTAs @3/SM, sequential acc+epilogue interleave ----
__global__ void __launch_bounds__(256, 3)
triplet_persist_kernel(float* __restrict__ out, int n, int nt, int nwork) {
    extern __shared__ char smem[];
    const uint32_t sbase = smem_u32(smem);
    const int tid = threadIdx.x;
    const int wid = tid >> 5;
    const int l   = tid & 31;

    float* sCbi   = (float*)(smem + SM_CBI);
    float* sn1bi  = (float*)(smem + SM_N1BI);
    float* sn2bi  = (float*)(smem + SM_N2BI);
    float* sCbjH  = (float*)(smem + SM_CBJH);
    float* sn1bjH = (float*)(smem + SM_N1BJH);
    float* sn2bjH = (float*)(smem + SM_N2BJH);
    unsigned int* srm_bi  = (unsigned int*)(smem + SM_RMI);
    unsigned int* srm_bjH = (unsigned int*)(smem + SM_RMJH);
    float* ssum = (float*)(smem + SM_SSUM);
    const uint32_t OPS = sbase + SM_OPS;

    __shared__ int s_w;

    const int wm = wid & 3;
    const int wn = wid >> 2;
    const int qr = l >> 2;
    const int qc = (l & 3) * 2;
    const int arow = wm * 32 + (l & 7) + ((l >> 3) & 1) * 8;
    const int akoff = (l >> 4) * 8;
    const int brow = wn * 32 + (l & 7) + ((l >> 4) << 3);
    const int bkoff = ((l >> 3) & 1) * 8;
    const int wm2 = wid & 1;
    const int wn2 = wid >> 1;
    const int arow2 = wm2 * 32 + (l & 7) + ((l >> 3) & 1) * 8;
    const int brow2 = wn2 * 32 + (l & 7) + ((l >> 4) << 3);

    if (tid == 0) s_w = (int)atomicAdd(&g_work, 1u);
    __syncthreads();
    int w = s_w;
    if (w < nwork) {
        int bi, bj, h; decode(w, nt, bi, bj, h);
        load_item(OPS, bi, bj, h, tid);                 // g0, g1 outstanding
    }

    while (w < nwork) {
        int bi, bj, h; decode(w, nt, bi, bj, h);
        const bool diag = (bi == bj);

        __syncthreads();
        if (tid < 128) {
            srm_bi[tid] = 0u;
            sCbi[tid]  = g_C[bi * TILE + tid];
            sn1bi[tid] = g_n1[bi * TILE + tid];
            sn2bi[tid] = g_n2[bi * TILE + tid];
        } else if (tid < 192) {
            int t = tid - 128;
            srm_bjH[t] = 0u;
            sCbjH[t]  = g_C[bj * TILE + h * 64 + t];
            sn1bjH[t] = g_n1[bj * TILE + h * 64 + t];
            sn2bjH[t] = g_n2[bj * TILE + h * 64 + t];
        } else if (tid == 255) {
            s_w = (int)atomicAdd(&g_work, 1u);          // ticket for NEXT item
        }

        float sum = 0.f;

        CP_WAIT1();             // g0 (A + B1) ready
        __syncthreads();        // publishes s_w too
        const int wn_next = s_w;

        // ---- acc1 = p1bi . p1bjH^T over full K; epilogue while B2 flies ----
        {
            float acc[2][4][4];
#pragma unroll
            for (int mf = 0; mf < 2; mf++)
#pragma unroll
                for (int nf = 0; nf < 4; nf++)
#pragma unroll
                    for (int e = 0; e < 4; e++) acc[mf][nf][e] = 0.f;
            group4(OPS + P1_AH, OPS + P1_B1H,        0,  arow, akoff, brow, bkoff, acc);
            group4(OPS + P1_AH, OPS + P1_B1H + 8192, 64, arow, akoff, brow, bkoff, acc);
            epi_normal(acc, sCbi, sn1bjH, wm, wn, qr, qc, l, diag,
                       bi * TILE, bj * TILE + h * 64, srm_bi, sum);
            if (!diag)
                epi_trans(acc, sCbjH, sn1bi, wm, wn, qr, qc, l, srm_bjH, sum);
        }

        CP_WAIT0();             // g1 (B2) ready
        __syncthreads();

        // ---- acc2 = p1bi . p2bjH^T over full K ----
        {
            float acc[2][4][4];
#pragma unroll
            for (int mf = 0; mf < 2; mf++)
#pragma unroll
                for (int nf = 0; nf < 4; nf++)
#pragma unroll
                    for (int e = 0; e < 4; e++) acc[mf][nf][e] = 0.f;
            group4(OPS + P1_AH, OPS + P1_B2H,        0,  arow, akoff, brow, bkoff, acc);
            group4(OPS + P1_AH, OPS + P1_B2H + 8192, 64, arow, akoff, brow, bkoff, acc);
            __syncthreads();    // all phase1 operand reads done

            if (diag) {
                if (wn_next < nwork) {
                    int nbi, nbj, nh; decode(wn_next, nt, nbi, nbj, nh);
                    load_item(OPS, nbi, nbj, nh, tid);
                }
                epi_normal(acc, sCbi, sn2bjH, wm, wn, qr, qc, l, true,
                           bi * TILE, bj * TILE + h * 64, srm_bi, sum);
            } else {
                // issue both phase2 buffers now (regions: buf0 over A, buf1 over A+B1)
                const size_t hoff0 = (size_t)(bj * 2 + 0) * CT + h * 8192;
                const size_t hoff1 = (size_t)(bj * 2 + 1) * CT + h * 8192;
                cpa(OPS + P2_BUF(0) + P2_A2H, g_img_p1h + hoff0, 8192, tid);
                cpa(OPS + P2_BUF(0) + P2_B2H, g_img_p2h + (size_t)(bi * 2 + 0) * CT, CT, tid);
                CP_COMMIT();
                cpa(OPS + P2_BUF(1) + P2_A2H, g_img_p1h + hoff1, 8192, tid);
                cpa(OPS + P2_BUF(1) + P2_B2H, g_img_p2h + (size_t)(bi * 2 + 1) * CT, CT, tid);
                CP_COMMIT();
                epi_normal(acc, sCbi, sn2bjH, wm, wn, qr, qc, l, false,
                           bi * TILE, bj * TILE + h * 64, srm_bi, sum);
            }
        }

        // ---- phase2: G2b = p1bjH . p2bi^T (off-diag only) ----
        if (!diag) {
            float acc[2][4][4];
#pragma unroll
            for (int mf = 0; mf < 2; mf++)
#pragma unroll
                for (int nf = 0; nf < 4; nf++)
#pragma unroll
                    for (int e = 0; e < 4; e++) acc[mf][nf][e] = 0.f;

            CP_WAIT1();         // buf0 ready, buf1 in flight
            __syncthreads();
            group4(OPS + P2_BUF(0) + P2_A2H, OPS + P2_BUF(0) + P2_B2H, 0,
                   arow2, akoff, brow2, bkoff, acc);
            CP_WAIT0();         // buf1 ready
            __syncthreads();
            group4(OPS + P2_BUF(1) + P2_A2H, OPS + P2_BUF(1) + P2_B2H, 0,
                   arow2, akoff, brow2, bkoff, acc);
            __syncthreads();    // all phase2 operand reads done

            if (wn_next < nwork) {
                int nbi, nbj, nh; decode(wn_next, nt, nbi, nbj, nh);
                load_item(OPS, nbi, nbj, nh, tid);
            }
            epi_normal(acc, sCbjH, sn2bi, wm2, wn2, qr, qc, l, false, 0, 0, srm_bjH, sum);
        }

        // ---- publish this item ----
#pragma unroll
        for (int m = 16; m; m >>= 1) sum += __shfl_xor_sync(0xffffffffu, sum, m);
        if (l == 0) ssum[wid] = sum;
        __syncthreads();
        if (tid < 128)
            atomicMax(&g_rowmax[bi * TILE + tid], srm_bi[tid]);
        else if (tid < 192)
            atomicMax(&g_rowmax[bj * TILE + h * 64 + (tid - 128)], srm_bjH[tid - 128]);
        if (tid == 0) {
            float t = 0.f;
#pragma unroll
            for (int ww = 0; ww < 8; ww++) t += ssum[ww];
            g_partial[w] = t;
        }
        w = wn_next;
    }

    // ---- CTA done; last CTA finalizes ----
    __threadfence();
    __shared__ unsigned int s_last;
    if (tid == 0) s_last = (atomicAdd(&g_done, 1u) == (unsigned)(gridDim.x - 1)) ? 1u : 0u;
    __syncthreads();
    if (!s_last) return;
    __threadfence();

    double smax = 0.0, ssumd = 0.0;
    for (int i = tid; i < n; i += 256) {
        smax += (double)__uint_as_float(g_rowmax[i]);
        g_rowmax[i] = 0u;
    }
    for (int i = tid; i < nwork; i += 256) ssumd += (double)g_partial[i];
#pragma unroll
    for (int m = 16; m; m >>= 1) {
        smax  += __shfl_xor_sync(0xffffffffu, smax, m);
        ssumd += __shfl_xor_sync(0xffffffffu, ssumd, m);
    }
    __shared__ double d1[8], d2[8];
    if (l == 0) { d1[wid] = smax; d2[wid] = ssumd; }
    __syncthreads();
    if (tid == 0) {
        double t1 = 0.0, t2 = 0.0;
#pragma unroll
        for (int ww = 0; ww < 8; ww++) { t1 += d1[ww]; t2 += d2[ww]; }
        out[0] = (float)(t1 / (double)n);
        out[1] = (float)(t2 / (2.0 * (double)n * (double)(n - 1)));
        g_work = 0u;
        g_done = 0u;
    }
}

extern "C" void kernel_launch(void* const* d_in, const int* in_sizes, int n_in,
                              void* d_out, int out_size) {
    const float* p1 = (const float*)d_in[0];
    const float* p2 = (const float*)d_in[1];
    float* out = (float*)d_out;
    const int n = in_sizes[0] / DIM;            // 4096
    const int nt = n / TILE;                    // 32
    const int nwork = nt * (nt + 1);            // 1056 half-pairs

    int nsm = 148;
    cudaDeviceGetAttribute(&nsm, cudaDevAttrMultiProcessorCount, 0);

    cudaFuncSetAttribute(triplet_persist_kernel,
                         cudaFuncAttributeMaxDynamicSharedMemorySize, SMEM_TOTAL);

    prep_kernel<<<n / 8, 256>>>(p1, p2, n);
    triplet_persist_kernel<<<nsm * 3, 256, SMEM_TOTAL>>>(out, n, nt, nwork);
}

// round 14
// speedup vs baseline: 1.4341x; 1.0393x over previous
#include <cuda_runtime.h>
#include <cuda_fp16.h>
#include <cstdint>

#define MARGIN 0.3f
#define DIM  128
#define TILE 128
#define MAXN 4096
#define MAXT (MAXN / TILE)
#define MAXPAIR (MAXT * (MAXT + 1) / 2)
#define CT   16384                 // image chunk tile: 128 rows x 64 fp16 cols (SW128)

// ---- dynamic smem layout (bytes) ----
#define SM_CBI   0                 // 128 f
#define SM_N1BI  512
#define SM_N2BI  1024
#define SM_CBJH  1536              // 64 f
#define SM_N1BJH 1792
#define SM_N2BJH 2048
#define SM_RMI   2304              // 128 u
#define SM_RMJH  2816              // 64 u
#define SM_SSUM  3072              // 8 f
#define SM_OPS   4096              // 64KB operand region, 1024-aligned
#define SMEM_TOTAL (SM_OPS + 64 * 1024)

// phase1 (all prefetched, hi only): A [0,32K) (c0,c1); B1 [32K,48K); B2 [48K,64K)
// phase2 (off-diag): p2bi (32K) reloaded into the A region; B1 region reused as B.
#define P1_AH  0
#define P1_B1H (32 * 1024)
#define P1_B2H (48 * 1024)

__device__ float g_n1[MAXN], g_n2[MAXN], g_C[MAXN];
__device__ unsigned int g_rowmax[MAXN];      // zero at load; finalizer re-zeros
__device__ float g_partial[2 * MAXPAIR];
__device__ unsigned int g_work;              // work ticket; finalizer re-zeros
__device__ unsigned int g_done;              // CTA done counter; finalizer re-zeros

// pre-swizzled fp16 hi images: [tile][chunk][16KB]
__device__ __align__(16) unsigned char g_img_p1h[MAXT * 2 * CT];
__device__ __align__(16) unsigned char g_img_p2h[MAXT * 2 * CT];

__device__ __forceinline__ uint32_t smem_u32(const void* p) {
    uint32_t a;
    asm("{ .reg .u64 t; cvta.to.shared.u64 t, %1; cvt.u32.u64 %0, t; }" : "=r"(a) : "l"(p));
    return a;
}
__device__ __forceinline__ int swz(int row, int kc) {
    int b = row * 128 + kc * 2;
    return b ^ ((b >> 3) & 0x70);
}
__device__ __forceinline__ uint32_t taddrA(uint32_t base0, int row, int kcol) {
    return base0 + ((kcol >> 6) << 14) + swz(row, kcol & 63);
}
__device__ __forceinline__ void ldsm4(uint32_t addr, uint32_t r[4]) {
    asm volatile("ldmatrix.sync.aligned.m8n8.x4.shared.b16 {%0,%1,%2,%3}, [%4];"
                 : "=r"(r[0]), "=r"(r[1]), "=r"(r[2]), "=r"(r[3]) : "r"(addr));
}
__device__ __forceinline__ void cp16(uint32_t saddr, const void* g) {
    asm volatile("cp.async.cg.shared.global [%0], [%1], 16;" :: "r"(saddr), "l"(g));
}
#define CP_COMMIT() asm volatile("cp.async.commit_group;" ::: "memory")
#define CP_WAIT0()  asm volatile("cp.async.wait_group 0;" ::: "memory")
#define CP_WAIT1()  asm volatile("cp.async.wait_group 1;" ::: "memory")

#define MMA(d, a, b)                                                               \
    asm volatile("mma.sync.aligned.m16n8k16.row.col.f32.f16.f16.f32 "              \
                 "{%0,%1,%2,%3},{%4,%5,%6,%7},{%8,%9},{%0,%1,%2,%3};"              \
                 : "+f"((d)[0]), "+f"((d)[1]), "+f"((d)[2]), "+f"((d)[3])          \
                 : "r"((a)[0]), "r"((a)[1]), "r"((a)[2]), "r"((a)[3]),             \
                   "r"((b)[0]), "r"((b)[1]))

union HU { __half2 h; uint32_t u; };

__device__ __forceinline__ void cpa(uint32_t sdst, const unsigned char* gsrc, int bytes, int tid) {
    for (int t = tid * 16; t < bytes; t += 4096) cp16(sdst + t, gsrc + t);
}

__device__ __forceinline__ void decode(int w, int nt, int& bi, int& bj, int& h) {
    int pairid = w >> 1;
    h = w & 1;
    bi = 0;
    int rem = pairid;
    while (rem >= nt - bi) { rem -= (nt - bi); bi++; }
    bj = bi + rem;
}

// phase1 prologue: g0 = A both chunks + B1 both chunks (48K); g1 = B2 both chunks (16K)
__device__ __forceinline__ void load_item(uint32_t OPS, int bi, int bj, int h, int tid) {
    size_t b0 = (size_t)(bj * 2 + 0) * CT + h * 8192;
    size_t b1 = (size_t)(bj * 2 + 1) * CT + h * 8192;
    cpa(OPS + P1_AH, g_img_p1h + (size_t)(bi * 2) * CT, 2 * CT, tid);
    cpa(OPS + P1_B1H,        g_img_p1h + b0, 8192, tid);
    cpa(OPS + P1_B1H + 8192, g_img_p1h + b1, 8192, tid);
    CP_COMMIT();                                                   // g0
    cpa(OPS + P1_B2H,        g_img_p2h + b0, 8192, tid);
    cpa(OPS + P1_B2H + 8192, g_img_p2h + b1, 8192, tid);
    CP_COMMIT();                                                   // g1
}

// 4 ksteps of one gram, hi-only: 4 ldsm.x4 -> 8 MMA per kstep
__device__ __forceinline__ void group4(
    uint32_t AH, uint32_t BH, int kAbase,
    int arow, int akoff, int brow, int bkoff, float (&acc)[2][4][4])
{
#pragma unroll
    for (int ks = 0; ks < 4; ks++) {
        const int kA = kAbase + ks * 16;
        const int kB = ks * 16;
        uint32_t ah[2][4];
#pragma unroll
        for (int mf = 0; mf < 2; mf++)
            ldsm4(taddrA(AH, arow + mf * 16, kA + akoff), ah[mf]);
        uint32_t bh[4][2];
#pragma unroll
        for (int np = 0; np < 2; np++) {
            uint32_t t4[4];
            ldsm4(BH + swz(brow + np * 16, kB + bkoff), t4);
            bh[2*np][0]=t4[0]; bh[2*np][1]=t4[1]; bh[2*np+1][0]=t4[2]; bh[2*np+1][1]=t4[3];
        }
#pragma unroll
        for (int mf = 0; mf < 2; mf++)
#pragma unroll
            for (int nf = 0; nf < 4; nf++)
                MMA(acc[mf][nf], ah[mf], bh[nf]);
    }
}

__device__ __forceinline__ void epi_normal(
    float (&acc)[2][4][4], const float* Crow, const float* ncol,
    int wm, int wn, int qr, int qc, int l, bool dz, int rbase, int cbase,
    unsigned int* srm, float& sum)
{
    float Cr[2][2], nc[4][2];
#pragma unroll
    for (int mf = 0; mf < 2; mf++) {
        int r0 = wm * 32 + mf * 16 + qr;
        Cr[mf][0] = Crow[r0]; Cr[mf][1] = Crow[r0 + 8];
    }
#pragma unroll
    for (int nf = 0; nf < 4; nf++) {
        int c0 = wn * 32 + nf * 8 + qc;
        nc[nf][0] = ncol[c0]; nc[nf][1] = ncol[c0 + 1];
    }
    float rmax[2][2] = {{0.f, 0.f}, {0.f, 0.f}};
#pragma unroll
    for (int mf = 0; mf < 2; mf++)
#pragma unroll
        for (int nf = 0; nf < 4; nf++)
#pragma unroll
            for (int e = 0; e < 4; e++) {
                int rr = e >> 1, cc = e & 1;
                float v = fmaxf(Cr[mf][rr] - nc[nf][cc] + 2.f * acc[mf][nf][e], 0.f);
                if (dz) {
                    int rl = rbase + wm * 32 + mf * 16 + qr + rr * 8;
                    int cl = cbase + wn * 32 + nf * 8 + qc + cc;
                    if (rl == cl) v = 0.f;
                }
                sum += v;
                rmax[mf][rr] = fmaxf(rmax[mf][rr], v);
            }
#pragma unroll
    for (int m = 1; m <= 2; m <<= 1)
#pragma unroll
        for (int mf = 0; mf < 2; mf++) {
            rmax[mf][0] = fmaxf(rmax[mf][0], __shfl_xor_sync(0xffffffffu, rmax[mf][0], m));
            rmax[mf][1] = fmaxf(rmax[mf][1], __shfl_xor_sync(0xffffffffu, rmax[mf][1], m));
        }
    if ((l & 3) == 0) {
#pragma unroll
        for (int mf = 0; mf < 2; mf++) {
            atomicMax(&srm[wm * 32 + mf * 16 + qr],     __float_as_uint(rmax[mf][0]));
            atomicMax(&srm[wm * 32 + mf * 16 + qr + 8], __float_as_uint(rmax[mf][1]));
        }
    }
}

__device__ __forceinline__ void epi_trans(
    float (&acc)[2][4][4], const float* Ccol, const float* nrow,
    int wm, int wn, int qr, int qc, int l,
    unsigned int* srm, float& sum)
{
    float Ct[4][2], nr[2][2];
#pragma unroll
    for (int nf = 0; nf < 4; nf++) {
        int c0 = wn * 32 + nf * 8 + qc;
        Ct[nf][0] = Ccol[c0]; Ct[nf][1] = Ccol[c0 + 1];
    }
#pragma unroll
    for (int mf = 0; mf < 2; mf++) {
        int r0 = wm * 32 + mf * 16 + qr;
        nr[mf][0] = nrow[r0]; nr[mf][1] = nrow[r0 + 8];
    }
    float cmax[4][2] = {{0.f,0.f},{0.f,0.f},{0.f,0.f},{0.f,0.f}};
#pragma unroll
    for (int mf = 0; mf < 2; mf++)
#pragma unroll
        for (int nf = 0; nf < 4; nf++)
#pragma unroll
            for (int e = 0; e < 4; e++) {
                int rr = e >> 1, cc = e & 1;
                float v = fmaxf(Ct[nf][cc] - nr[mf][rr] + 2.f * acc[mf][nf][e], 0.f);
                sum += v;
                cmax[nf][cc] = fmaxf(cmax[nf][cc], v);
            }
#pragma unroll
    for (int m = 4; m <= 16; m <<= 1)
#pragma unroll
        for (int nf = 0; nf < 4; nf++) {
            cmax[nf][0] = fmaxf(cmax[nf][0], __shfl_xor_sync(0xffffffffu, cmax[nf][0], m));
            cmax[nf][1] = fmaxf(cmax[nf][1], __shfl_xor_sync(0xffffffffu, cmax[nf][1], m));
        }
    if (l < 4) {
#pragma unroll
        for (int nf = 0; nf < 4; nf++) {
            int c0 = wn * 32 + nf * 8 + qc;
            atomicMax(&srm[c0],     __float_as_uint(cmax[nf][0]));
            atomicMax(&srm[c0 + 1], __float_as_uint(cmax[nf][1]));
        }
    }
}

// ---- prep: norms/C + pre-swizzled fp16 hi images ----
__global__ void __launch_bounds__(256)
prep_kernel(const float* __restrict__ p1, const float* __restrict__ p2, int n) {
    int row = blockIdx.x * 8 + (threadIdx.x >> 5);
    int lane = threadIdx.x & 31;
    if (row >= n) return;
    float4 a = ((const float4*)(p1 + (size_t)row * DIM))[lane];
    float4 b = ((const float4*)(p2 + (size_t)row * DIM))[lane];

    float n1 = a.x*a.x + a.y*a.y + a.z*a.z + a.w*a.w;
    float n2 = b.x*b.x + b.y*b.y + b.z*b.z + b.w*b.w;
    float dx = a.x-b.x, dy = a.y-b.y, dz = a.z-b.z, dw = a.w-b.w;
    float dap = dx*dx + dy*dy + dz*dz + dw*dw;
#pragma unroll
    for (int m = 16; m; m >>= 1) {
        n1 += __shfl_xor_sync(0xffffffffu, n1, m);
        n2 += __shfl_xor_sync(0xffffffffu, n2, m);
        dap += __shfl_xor_sync(0xffffffffu, dap, m);
    }
    if (lane == 0) {
        g_n1[row] = n1; g_n2[row] = n2; g_C[row] = dap - n1 + MARGIN;
    }

    int tile = row >> 7, lr = row & 127;
    int c4 = lane * 4, chunk = c4 >> 6, lc = c4 & 63;
    size_t off = (size_t)(tile * 2 + chunk) * CT + swz(lr, lc);

    HU h0, h1;
    h0.h = __floats2half2_rn(a.x, a.y);
    h1.h = __floats2half2_rn(a.z, a.w);
    *(uint2*)(g_img_p1h + off) = make_uint2(h0.u, h1.u);
    h0.h = __floats2half2_rn(b.x, b.y);
    h1.h = __floats2half2_rn(b.z, b.w);
    *(uint2*)(g_img_p2h + off) = make_uint2(h0.u, h1.u);
}

// ---- main: persistent CTAs @3/SM, transposed phase2 reusing resident B1 ----
__global__ void __launch_bounds__(256, 3)
triplet_persist_kernel(float* __restrict__ out, int n, int nt, int nwork) {
    extern __shared__ char smem[];
    const uint32_t sbase = smem_u32(smem);
    const int tid = threadIdx.x;
    const int wid = tid >> 5;
    const int l   = tid & 31;

    float* sCbi   = (float*)(smem + SM_CBI);
    float* sn1bi  = (float*)(smem + SM_N1BI);
    float* sn2bi  = (float*)(smem + SM_N2BI);
    float* sCbjH  = (float*)(smem + SM_CBJH);
    float* sn1bjH = (float*)(smem + SM_N1BJH);
    float* sn2bjH = (float*)(smem + SM_N2BJH);
    unsigned int* srm_bi  = (unsigned int*)(smem + SM_RMI);
    unsigned int* srm_bjH = (unsigned int*)(smem + SM_RMJH);
    float* ssum = (float*)(smem + SM_SSUM);
    const uint32_t OPS = sbase + SM_OPS;

    __shared__ int s_w;

    const int wm = wid & 3;
    const int wn = wid >> 2;
    const int qr = l >> 2;
    const int qc = (l & 3) * 2;
    const int arow = wm * 32 + (l & 7) + ((l >> 3) & 1) * 8;
    const int akoff = (l >> 4) * 8;
    const int brow = wn * 32 + (l & 7) + ((l >> 4) << 3);
    const int bkoff = ((l >> 3) & 1) * 8;

    if (tid == 0) s_w = (int)atomicAdd(&g_work, 1u);
    __syncthreads();
    int w = s_w;
    if (w < nwork) {
        int bi, bj, h; decode(w, nt, bi, bj, h);
        load_item(OPS, bi, bj, h, tid);                 // g0, g1 outstanding
    }

    while (w < nwork) {
        int bi, bj, h; decode(w, nt, bi, bj, h);
        const bool diag = (bi == bj);

        __syncthreads();
        if (tid < 128) {
            srm_bi[tid] = 0u;
            sCbi[tid]  = g_C[bi * TILE + tid];
            sn1bi[tid] = g_n1[bi * TILE + tid];
            sn2bi[tid] = g_n2[bi * TILE + tid];
        } else if (tid < 192) {
            int t = tid - 128;
            srm_bjH[t] = 0u;
            sCbjH[t]  = g_C[bj * TILE + h * 64 + t];
            sn1bjH[t] = g_n1[bj * TILE + h * 64 + t];
            sn2bjH[t] = g_n2[bj * TILE + h * 64 + t];
        } else if (tid == 255) {
            s_w = (int)atomicAdd(&g_work, 1u);          // ticket for NEXT item
        }

        float sum = 0.f;

        CP_WAIT1();             // g0 (A + B1) ready
        __syncthreads();        // publishes s_w too
        const int wn_next = s_w;

        // ---- acc1 = p1bi . p1bjH^T over full K; epilogue covers B2 flight ----
        {
            float acc[2][4][4];
#pragma unroll
            for (int mf = 0; mf < 2; mf++)
#pragma unroll
                for (int nf = 0; nf < 4; nf++)
#pragma unroll
                    for (int e = 0; e < 4; e++) acc[mf][nf][e] = 0.f;
            group4(OPS + P1_AH, OPS + P1_B1H,        0,  arow, akoff, brow, bkoff, acc);
            group4(OPS + P1_AH, OPS + P1_B1H + 8192, 64, arow, akoff, brow, bkoff, acc);
            epi_normal(acc, sCbi, sn1bjH, wm, wn, qr, qc, l, diag,
                       bi * TILE, bj * TILE + h * 64, srm_bi, sum);
            if (!diag)
                epi_trans(acc, sCbjH, sn1bi, wm, wn, qr, qc, l, srm_bjH, sum);
        }

        CP_WAIT0();             // g1 (B2) ready
        __syncthreads();

        // ---- acc2 = p1bi . p2bjH^T over full K ----
        {
            float acc[2][4][4];
#pragma unroll
            for (int mf = 0; mf < 2; mf++)
#pragma unroll
                for (int nf = 0; nf < 4; nf++)
#pragma unroll
                    for (int e = 0; e < 4; e++) acc[mf][nf][e] = 0.f;
            group4(OPS + P1_AH, OPS + P1_B2H,        0,  arow, akoff, brow, bkoff, acc);
            group4(OPS + P1_AH, OPS + P1_B2H + 8192, 64, arow, akoff, brow, bkoff, acc);
            __syncthreads();    // A-region reads done (B1 stays resident)

            if (diag) {
                if (wn_next < nwork) {
                    int nbi, nbj, nh; decode(wn_next, nt, nbi, nbj, nh);
                    load_item(OPS, nbi, nbj, nh, tid);
                }
                epi_normal(acc, sCbi, sn2bjH, wm, wn, qr, qc, l, true,
                           bi * TILE, bj * TILE + h * 64, srm_bi, sum);
            } else {
                // phase2 operand: p2bi (both chunks) into the freed A region
                cpa(OPS + P1_AH, g_img_p2h + (size_t)(bi * 2) * CT, 2 * CT, tid);
                CP_COMMIT();
                epi_normal(acc, sCbi, sn2bjH, wm, wn, qr, qc, l, false,
                           bi * TILE, bj * TILE + h * 64, srm_bi, sum);
            }
        }

        // ---- phase2 (off-diag): G2b^T = p2bi . p1bjH^T (B1 region reused) ----
        if (!diag) {
            float acc[2][4][4];
#pragma unroll
            for (int mf = 0; mf < 2; mf++)
#pragma unroll
                for (int nf = 0; nf < 4; nf++)
#pragma unroll
                    for (int e = 0; e < 4; e++) acc[mf][nf][e] = 0.f;

            CP_WAIT0();         // p2bi ready
            __syncthreads();
            group4(OPS + P1_AH, OPS + P1_B1H,        0,  arow, akoff, brow, bkoff, acc);
            group4(OPS + P1_AH, OPS + P1_B1H + 8192, 64, arow, akoff, brow, bkoff, acc);
            __syncthreads();    // all phase2 operand reads done

            if (wn_next < nwork) {
                int nbi, nbj, nh; decode(wn_next, nt, nbi, nbj, nh);
                load_item(OPS, nbi, nbj, nh, tid);
            }
            // transposed epilogue: cols anchored by C[bjH], rows give n2[bi]
            epi_trans(acc, sCbjH, sn2bi, wm, wn, qr, qc, l, srm_bjH, sum);
        }

        // ---- publish this item ----
#pragma unroll
        for (int m = 16; m; m >>= 1) sum += __shfl_xor_sync(0xffffffffu, sum, m);
        if (l == 0) ssum[wid] = sum;
        __syncthreads();
        if (tid < 128)
            atomicMax(&g_rowmax[bi * TILE + tid], srm_bi[tid]);
        else if (tid < 192)
            atomicMax(&g_rowmax[bj * TILE + h * 64 + (tid - 128)], srm_bjH[tid - 128]);
        if (tid == 0) {
            float t = 0.f;
#pragma unroll
            for (int ww = 0; ww < 8; ww++) t += ssum[ww];
            g_partial[w] = t;
        }
        w = wn_next;
    }

    // ---- CTA done; last CTA finalizes ----
    __threadfence();
    __shared__ unsigned int s_last;
    if (tid == 0) s_last = (atomicAdd(&g_done, 1u) == (unsigned)(gridDim.x - 1)) ? 1u : 0u;
    __syncthreads();
    if (!s_last) return;
    __threadfence();

    double smax = 0.0, ssumd = 0.0;
    for (int i = tid; i < n; i += 256) {
        smax += (double)__uint_as_float(g_rowmax[i]);
        g_rowmax[i] = 0u;
    }
    for (int i = tid; i < nwork; i += 256) ssumd += (double)g_partial[i];
#pragma unroll
    for (int m = 16; m; m >>= 1) {
        smax  += __shfl_xor_sync(0xffffffffu, smax, m);
        ssumd += __shfl_xor_sync(0xffffffffu, ssumd, m);
    }
    __shared__ double d1[8], d2[8];
    if (l == 0) { d1[wid] = smax; d2[wid] = ssumd; }
    __syncthreads();
    if (tid == 0) {
        double t1 = 0.0, t2 = 0.0;
#pragma unroll
        for (int ww = 0; ww < 8; ww++) { t1 += d1[ww]; t2 += d2[ww]; }
        out[0] = (float)(t1 / (double)n);
        out[1] = (float)(t2 / (2.0 * (double)n * (double)(n - 1)));
        g_work = 0u;
        g_done = 0u;
    }
}

extern "C" void kernel_launch(void* const* d_in, const int* in_sizes, int n_in,
                              void* d_out, int out_size) {
    const float* p1 = (const float*)d_in[0];
    const float* p2 = (const float*)d_in[1];
    float* out = (float*)d_out;
    const int n = in_sizes[0] / DIM;            // 4096
    const int nt = n / TILE;                    // 32
    const int nwork = nt * (nt + 1);            // 1056 half-pairs

    int nsm = 148;
    cudaDeviceGetAttribute(&nsm, cudaDevAttrMultiProcessorCount, 0);

    cudaFuncSetAttribute(triplet_persist_kernel,
                         cudaFuncAttributeMaxDynamicSharedMemorySize, SMEM_TOTAL);

    prep_kernel<<<n / 8, 256>>>(p1, p2, n);
    triplet_persist_kernel<<<nsm * 3, 256, SMEM_TOTAL>>>(out, n, nt, nwork);
}